// round 4
// baseline (speedup 1.0000x reference)
#include <cuda_runtime.h>
#include <cstdint>
#include <cstddef>

#define BB 32
#define SS 64
#define TT 64
#define HH 1024
#define VV 32000
#define G3H 3072

// ---------------- scratch (device globals; no allocation allowed) ----------------
__device__ float g_Uk[BB * SS * HH];        // Ua(keys):  [B,S,H]
__device__ float g_X[TT * BB * HH];         // gathered embeddings, row r = t*32+b
__device__ float g_GiX[TT * BB * G3H];      // x-part of GRU input gates (+b_ih)
__device__ float g_Hall[TT * BB * HH];      // hidden states per step
__device__ float g_Q[BB * HH];              // Wa(hid)
__device__ float g_GH[BB * G3H];            // hid @ W_hh^T + b_hh
__device__ float g_GI[BB * G3H];            // gi_x + ctx @ W_ih[:,H:]^T
__device__ float g_Ctx[BB * HH];            // attention context

// ---------------- packed f32x2 helpers (FFMA2: 2x fp32 rate on sm_103a) ----------
__device__ __forceinline__ unsigned long long pk2(float lo, float hi) {
    unsigned long long r;
    asm("mov.b64 %0, {%1, %2};" : "=l"(r) : "f"(lo), "f"(hi));
    return r;
}
__device__ __forceinline__ void upk2(unsigned long long v, float& lo, float& hi) {
    asm("mov.b64 {%0, %1}, %2;" : "=f"(lo), "=f"(hi) : "l"(v));
}
__device__ __forceinline__ void ffma2(unsigned long long& c, unsigned long long a,
                                      unsigned long long b) {
    asm("fma.rn.f32x2 %0, %1, %2, %0;" : "+l"(c) : "l"(a), "l"(b));
}

// ---------------- big GEMM: C[M,N] = A[M,K=1024] * W[N,K]^T + bias -----------------
// 128x128 block tile, kc=16, 256 threads, 8x8 microtile with packed FMA.
// mode 0: C row-major with ld=N.  mode 1: logits remap row r=t*32+b -> out[b,t,:].
__global__ __launch_bounds__(256)
void gemm128(const float* __restrict__ A, const float* __restrict__ W, int ldw,
             const float* __restrict__ bias, float* __restrict__ C, int N, int mode)
{
    __shared__ float As[16][132];
    __shared__ float Ws[16][132];
    const int tid = threadIdx.x;
    const int m0 = blockIdx.y * 128;
    const int n0 = blockIdx.x * 128;
    const int lm = tid >> 2;             // 0..63 (loader row)
    const int lk = (tid & 3) << 2;       // 0,4,8,12 (loader k)
    const int mi = (tid >> 4) << 3;      // microtile m base
    const int ni = (tid & 15) << 3;      // microtile n base

    unsigned long long acc[8][4];
#pragma unroll
    for (int i = 0; i < 8; i++)
#pragma unroll
        for (int j = 0; j < 4; j++) acc[i][j] = 0ull;

    for (int kt = 0; kt < HH; kt += 16) {
        float4 a0 = *(const float4*)(A + (size_t)(m0 + lm) * HH + kt + lk);
        float4 a1 = *(const float4*)(A + (size_t)(m0 + lm + 64) * HH + kt + lk);
        float4 w0 = *(const float4*)(W + (size_t)(n0 + lm) * ldw + kt + lk);
        float4 w1 = *(const float4*)(W + (size_t)(n0 + lm + 64) * ldw + kt + lk);
        __syncthreads();
        As[lk + 0][lm] = a0.x; As[lk + 1][lm] = a0.y;
        As[lk + 2][lm] = a0.z; As[lk + 3][lm] = a0.w;
        As[lk + 0][lm + 64] = a1.x; As[lk + 1][lm + 64] = a1.y;
        As[lk + 2][lm + 64] = a1.z; As[lk + 3][lm + 64] = a1.w;
        Ws[lk + 0][lm] = w0.x; Ws[lk + 1][lm] = w0.y;
        Ws[lk + 2][lm] = w0.z; Ws[lk + 3][lm] = w0.w;
        Ws[lk + 0][lm + 64] = w1.x; Ws[lk + 1][lm + 64] = w1.y;
        Ws[lk + 2][lm + 64] = w1.z; Ws[lk + 3][lm + 64] = w1.w;
        __syncthreads();
#pragma unroll
        for (int k = 0; k < 16; k++) {
            float4 aA = *(const float4*)&As[k][mi];
            float4 aB = *(const float4*)&As[k][mi + 4];
            float4 wA = *(const float4*)&Ws[k][ni];
            float4 wB = *(const float4*)&Ws[k][ni + 4];
            unsigned long long w01 = pk2(wA.x, wA.y), w23 = pk2(wA.z, wA.w);
            unsigned long long w45 = pk2(wB.x, wB.y), w67 = pk2(wB.z, wB.w);
            float am[8] = {aA.x, aA.y, aA.z, aA.w, aB.x, aB.y, aB.z, aB.w};
#pragma unroll
            for (int i = 0; i < 8; i++) {
                unsigned long long ad = pk2(am[i], am[i]);
                ffma2(acc[i][0], ad, w01);
                ffma2(acc[i][1], ad, w23);
                ffma2(acc[i][2], ad, w45);
                ffma2(acc[i][3], ad, w67);
            }
        }
    }
#pragma unroll
    for (int i = 0; i < 8; i++) {
        int m = m0 + mi + i;
        float* crow;
        if (mode == 1) {
            int t = m >> 5, b = m & 31;
            crow = C + (size_t)b * ((size_t)TT * VV) + (size_t)t * VV;
        } else {
            crow = C + (size_t)m * N;
        }
#pragma unroll
        for (int j = 0; j < 4; j++) {
            float lo, hi;
            upk2(acc[i][j], lo, hi);
            int n = n0 + ni + j * 2;
            crow[n] = lo + bias[n];
            crow[n + 1] = hi + bias[n + 1];
        }
    }
}

// ---------------- skinny GEMM body: C[32 x 16cols] = A[32,1024] * W^T ------------
// 128 threads, kc=64. Optional bias[n] and init (row-major, ldi) addend.
__device__ __forceinline__ void skinny_body(
    const float* __restrict__ A, const float* __restrict__ W, int ldw, int n0,
    const float* __restrict__ bias, const float* __restrict__ init, int ldi,
    float* __restrict__ C, int ldc)
{
    __shared__ float Hs[64][36];
    __shared__ float Wsm[16][65];
    const int tid = threadIdx.x;         // 128 threads
    const int arow = tid >> 2;           // 0..31
    const int akq = (tid & 3) << 4;      // 0,16,32,48
    const int wn = tid >> 3;             // 0..15
    const int wkq = (tid & 7) << 3;      // 0..56
    const int n = tid & 15;
    const int m = (tid >> 4) << 2;       // 0,4,...,28

    unsigned long long acc01 = 0ull, acc23 = 0ull;

    for (int kt = 0; kt < HH; kt += 64) {
        float4 av[4];
#pragma unroll
        for (int j = 0; j < 4; j++)
            av[j] = *(const float4*)(A + (size_t)arow * HH + kt + akq + j * 4);
        float4 wv0 = *(const float4*)(W + (size_t)(n0 + wn) * ldw + kt + wkq);
        float4 wv1 = *(const float4*)(W + (size_t)(n0 + wn) * ldw + kt + wkq + 4);
        __syncthreads();
#pragma unroll
        for (int j = 0; j < 4; j++) {
            Hs[akq + j * 4 + 0][arow] = av[j].x;
            Hs[akq + j * 4 + 1][arow] = av[j].y;
            Hs[akq + j * 4 + 2][arow] = av[j].z;
            Hs[akq + j * 4 + 3][arow] = av[j].w;
        }
        Wsm[wn][wkq + 0] = wv0.x; Wsm[wn][wkq + 1] = wv0.y;
        Wsm[wn][wkq + 2] = wv0.z; Wsm[wn][wkq + 3] = wv0.w;
        Wsm[wn][wkq + 4] = wv1.x; Wsm[wn][wkq + 5] = wv1.y;
        Wsm[wn][wkq + 6] = wv1.z; Wsm[wn][wkq + 7] = wv1.w;
        __syncthreads();
#pragma unroll 16
        for (int k = 0; k < 64; k++) {
            float4 a = *(const float4*)&Hs[k][m];
            float w = Wsm[n][k];
            unsigned long long wd = pk2(w, w);
            ffma2(acc01, pk2(a.x, a.y), wd);
            ffma2(acc23, pk2(a.z, a.w), wd);
        }
    }
    float r0, r1, r2, r3;
    upk2(acc01, r0, r1);
    upk2(acc23, r2, r3);
    float res[4] = {r0, r1, r2, r3};
    const int nn = n0 + n;
    const float bv = bias ? bias[nn] : 0.f;
#pragma unroll
    for (int i = 0; i < 4; i++) {
        float v = res[i] + bv;
        if (init) v += init[(size_t)(m + i) * ldi + nn];
        C[(size_t)(m + i) * ldc + nn] = v;
    }
}

// q = hid@Wa^T + Wa_b (blocks 0..63) ; GH = hid@W_hh^T + b_hh (blocks 64..255)
__global__ __launch_bounds__(128)
void step_qgh(const float* __restrict__ hid,
              const float* __restrict__ Wa_w, const float* __restrict__ Wa_b,
              const float* __restrict__ W_hh, const float* __restrict__ b_hh)
{
    int blk = blockIdx.x;
    if (blk < 64)
        skinny_body(hid, Wa_w, HH, blk * 16, Wa_b, nullptr, 0, g_Q, HH);
    else
        skinny_body(hid, W_hh, HH, (blk - 64) * 16, b_hh, nullptr, 0, g_GH, G3H);
}

// GI = gi_x(t) + ctx @ W_ih[:, H:]^T     (b_ih already folded into gi_x)
__global__ __launch_bounds__(128)
void step_gi(const float* __restrict__ Wih_ctx, const float* __restrict__ giX_t)
{
    skinny_body(g_Ctx, Wih_ctx, 2 * HH, blockIdx.x * 16, nullptr, giX_t, G3H, g_GI, G3H);
}

// Bahdanau attention: scores -> softmax -> attentions output + context vector
__global__ __launch_bounds__(256)
void step_attn(const float* __restrict__ enc, const float* __restrict__ Va_w,
               const float* __restrict__ Va_b, float* __restrict__ attn_out, int t)
{
    __shared__ float qs[HH];
    __shared__ float sc[SS];
    __shared__ float wgt[SS];
    const int b = blockIdx.x, tid = threadIdx.x;
    for (int h = tid; h < HH; h += 256) qs[h] = g_Q[b * HH + h];
    __syncthreads();
    const int warp = tid >> 5, lane = tid & 31;
    for (int i = 0; i < 8; i++) {
        int s = i * 8 + warp;
        const float* uk = g_Uk + (size_t)(b * SS + s) * HH;
        float sum = 0.f;
        for (int h = lane; h < HH; h += 32)
            sum += Va_w[h] * tanhf(qs[h] + uk[h]);
#pragma unroll
        for (int o = 16; o; o >>= 1) sum += __shfl_xor_sync(0xffffffffu, sum, o);
        if (lane == 0) sc[s] = sum + Va_b[0];
    }
    __syncthreads();
    if (tid < 32) {
        float a = sc[tid], c = sc[tid + 32];
        float mx = fmaxf(a, c);
#pragma unroll
        for (int o = 16; o; o >>= 1) mx = fmaxf(mx, __shfl_xor_sync(0xffffffffu, mx, o));
        float e0 = expf(a - mx), e1 = expf(c - mx);
        float sm = e0 + e1;
#pragma unroll
        for (int o = 16; o; o >>= 1) sm += __shfl_xor_sync(0xffffffffu, sm, o);
        float inv = 1.f / sm;
        wgt[tid] = e0 * inv;
        wgt[tid + 32] = e1 * inv;
        attn_out[(size_t)b * TT * SS + (size_t)t * SS + tid] = e0 * inv;
        attn_out[(size_t)b * TT * SS + (size_t)t * SS + tid + 32] = e1 * inv;
    }
    __syncthreads();
    for (int h = tid; h < HH; h += 256) {
        float accv = 0.f;
        const float* eb = enc + (size_t)b * SS * HH + h;
#pragma unroll 8
        for (int s = 0; s < SS; s++) accv += wgt[s] * eb[(size_t)s * HH];
        g_Ctx[b * HH + h] = accv;
    }
}

// GRU gate combine (PyTorch semantics)
__global__ __launch_bounds__(1024)
void step_gru(const float* __restrict__ hid, float* __restrict__ hout,
              float* __restrict__ hT_out)
{
    const int b = blockIdx.x, h = threadIdx.x;
    float ir = g_GI[b * G3H + h],          hr = g_GH[b * G3H + h];
    float iz = g_GI[b * G3H + HH + h],     hz = g_GH[b * G3H + HH + h];
    float in_ = g_GI[b * G3H + 2 * HH + h], hn = g_GH[b * G3H + 2 * HH + h];
    float r = 1.f / (1.f + expf(-(ir + hr)));
    float z = 1.f / (1.f + expf(-(iz + hz)));
    float nv = tanhf(in_ + r * hn);
    float hp = hid[b * HH + h];
    float hnew = (1.f - z) * nv + z * hp;
    hout[b * HH + h] = hnew;
    if (hT_out) hT_out[b * HH + h] = hnew;
}

// teacher-forced tokens: tok(b,0)=SOS=1, tok(b,t)=target[b,t-1]; gather emb rows
__global__ __launch_bounds__(256)
void gather_emb(const int* __restrict__ target, const float* __restrict__ emb)
{
    const int r = blockIdx.x;            // r = t*32 + b
    const int t = r >> 5, b = r & 31;
    const int tok = (t == 0) ? 1 : target[b * TT + (t - 1)];
    const float4* src = (const float4*)(emb + (size_t)tok * HH);
    float4* dst = (float4*)(g_X + (size_t)r * HH);
    dst[threadIdx.x] = src[threadIdx.x];
}

extern "C" void kernel_launch(void* const* d_in, const int* in_sizes, int n_in,
                              void* d_out, int out_size)
{
    (void)in_sizes; (void)n_in; (void)out_size;
    const float* enc   = (const float*)d_in[0];
    const float* h0    = (const float*)d_in[1];   // [1,B,H] -> [B,H]
    const int*   tgt   = (const int*)d_in[2];
    const float* emb   = (const float*)d_in[3];
    const float* Wa_w  = (const float*)d_in[4];
    const float* Wa_b  = (const float*)d_in[5];
    const float* Ua_w  = (const float*)d_in[6];
    const float* Ua_b  = (const float*)d_in[7];
    const float* Va_w  = (const float*)d_in[8];
    const float* Va_b  = (const float*)d_in[9];
    const float* W_ih  = (const float*)d_in[10];
    const float* W_hh  = (const float*)d_in[11];
    const float* b_ih  = (const float*)d_in[12];
    const float* b_hh  = (const float*)d_in[13];
    const float* out_w = (const float*)d_in[14];
    const float* out_b = (const float*)d_in[15];

    float* out = (float*)d_out;
    float* dec_out  = out;                                        // B*T*V
    float* hT_out   = out + (size_t)BB * TT * VV;                 // B*H
    float* attn_out = out + (size_t)BB * TT * VV + (size_t)BB * HH; // B*T*S

    float *Uk, *X, *GiX, *Hall;
    cudaGetSymbolAddress((void**)&Uk, g_Uk);
    cudaGetSymbolAddress((void**)&X, g_X);
    cudaGetSymbolAddress((void**)&GiX, g_GiX);
    cudaGetSymbolAddress((void**)&Hall, g_Hall);

    // Phase 0: loop-invariant precomputation
    gather_emb<<<TT * BB, 256>>>(tgt, emb);
    gemm128<<<dim3(HH / 128, (BB * SS) / 128), 256>>>(enc, Ua_w, HH, Ua_b, Uk, HH, 0);
    gemm128<<<dim3(G3H / 128, (TT * BB) / 128), 256>>>(X, W_ih, 2 * HH, b_ih, GiX, G3H, 0);

    // Phase 1: sequential recurrence (4 launches/step)
    for (int t = 0; t < TT; t++) {
        const float* hid = (t == 0) ? h0 : (Hall + (size_t)(t - 1) * BB * HH);
        step_qgh<<<256, 128>>>(hid, Wa_w, Wa_b, W_hh, b_hh);
        step_attn<<<BB, 256>>>(enc, Va_w, Va_b, attn_out, t);
        step_gi<<<G3H / 16, 128>>>(W_ih + HH, GiX + (size_t)t * BB * G3H);
        step_gru<<<BB, 1024>>>(hid, Hall + (size_t)t * BB * HH,
                               (t == TT - 1) ? hT_out : nullptr);
    }

    // Phase 2: one batched vocab projection for all 64 steps (out_w read ONCE)
    gemm128<<<dim3(VV / 128, (TT * BB) / 128), 256>>>(Hall, out_w, HH, out_b,
                                                      dec_out, VV, 1);
}

// round 8
// speedup vs baseline: 1.2123x; 1.2123x over previous
#include <cuda_runtime.h>
#include <cstdint>
#include <cstddef>

#define BB 32
#define SS 64
#define TT 64
#define HH 1024
#define VV 32000
#define G3H 3072
#define NBLK 148
#define KC 128

// ---------------- scratch (device globals; no allocation allowed) ----------------
__device__ float g_Uk[BB * SS * HH];
__device__ float g_X[TT * BB * HH];
__device__ float g_GiX[TT * BB * G3H];
__device__ float g_Hall[TT * BB * HH];
__device__ float g_Q[BB * HH];
__device__ float g_GH[BB * G3H];
__device__ float g_GI[BB * G3H];
__device__ float g_Ctx[BB * HH];
__device__ float g_Sc[BB * SS];
__device__ unsigned g_arrive;

// ---------------- helpers ----------------
typedef unsigned long long ull;
struct __align__(16) ULL2 { ull x, y; };

__device__ __forceinline__ ull pk2(float lo, float hi) {
    ull r; asm("mov.b64 %0, {%1, %2};" : "=l"(r) : "f"(lo), "f"(hi)); return r;
}
__device__ __forceinline__ void upk2(ull v, float& lo, float& hi) {
    asm("mov.b64 {%0, %1}, %2;" : "=f"(lo), "=f"(hi) : "l"(v));
}
__device__ __forceinline__ void ffma2(ull& c, ull a, ull b) {
    asm("fma.rn.f32x2 %0, %1, %2, %0;" : "+l"(c) : "l"(a), "l"(b));
}
__device__ __forceinline__ float tanh_ap(float x) {
    float y; asm("tanh.approx.f32 %0, %1;" : "=f"(y) : "f"(x)); return y;
}
__device__ __forceinline__ unsigned ld_acq(unsigned* p) {
    unsigned v;
    asm volatile("ld.acquire.gpu.global.u32 %0, [%1];" : "=r"(v) : "l"(p) : "memory");
    return v;
}
// grid-wide barrier: monotonic counter, target = barrier_number * NBLK
__device__ __forceinline__ void gridbar(unsigned target) {
    __syncthreads();
    if (threadIdx.x == 0) {
        __threadfence();
        atomicAdd(&g_arrive, 1u);
        while (ld_acq(&g_arrive) < target) { __nanosleep(64); }
    }
    __syncthreads();
}

// ---------------- big GEMM (unchanged, passing): C = A[M,1024]*W[N,K]^T + bias ----
__global__ __launch_bounds__(256)
void gemm128(const float* __restrict__ A, const float* __restrict__ W, int ldw,
             const float* __restrict__ bias, float* __restrict__ C, int N, int mode)
{
    __shared__ float As[16][132];
    __shared__ float Ws[16][132];
    const int tid = threadIdx.x;
    const int m0 = blockIdx.y * 128;
    const int n0 = blockIdx.x * 128;
    const int lm = tid >> 2;
    const int lk = (tid & 3) << 2;
    const int mi = (tid >> 4) << 3;
    const int ni = (tid & 15) << 3;

    ull acc[8][4];
#pragma unroll
    for (int i = 0; i < 8; i++)
#pragma unroll
        for (int j = 0; j < 4; j++) acc[i][j] = 0ull;

    for (int kt = 0; kt < HH; kt += 16) {
        float4 a0 = *(const float4*)(A + (size_t)(m0 + lm) * HH + kt + lk);
        float4 a1 = *(const float4*)(A + (size_t)(m0 + lm + 64) * HH + kt + lk);
        float4 w0 = *(const float4*)(W + (size_t)(n0 + lm) * ldw + kt + lk);
        float4 w1 = *(const float4*)(W + (size_t)(n0 + lm + 64) * ldw + kt + lk);
        __syncthreads();
        As[lk + 0][lm] = a0.x; As[lk + 1][lm] = a0.y;
        As[lk + 2][lm] = a0.z; As[lk + 3][lm] = a0.w;
        As[lk + 0][lm + 64] = a1.x; As[lk + 1][lm + 64] = a1.y;
        As[lk + 2][lm + 64] = a1.z; As[lk + 3][lm + 64] = a1.w;
        Ws[lk + 0][lm] = w0.x; Ws[lk + 1][lm] = w0.y;
        Ws[lk + 2][lm] = w0.z; Ws[lk + 3][lm] = w0.w;
        Ws[lk + 0][lm + 64] = w1.x; Ws[lk + 1][lm + 64] = w1.y;
        Ws[lk + 2][lm + 64] = w1.z; Ws[lk + 3][lm + 64] = w1.w;
        __syncthreads();
#pragma unroll
        for (int k = 0; k < 16; k++) {
            float4 aA = *(const float4*)&As[k][mi];
            float4 aB = *(const float4*)&As[k][mi + 4];
            float4 wA = *(const float4*)&Ws[k][ni];
            float4 wB = *(const float4*)&Ws[k][ni + 4];
            ull w01 = pk2(wA.x, wA.y), w23 = pk2(wA.z, wA.w);
            ull w45 = pk2(wB.x, wB.y), w67 = pk2(wB.z, wB.w);
            float am[8] = {aA.x, aA.y, aA.z, aA.w, aB.x, aB.y, aB.z, aB.w};
#pragma unroll
            for (int i = 0; i < 8; i++) {
                ull ad = pk2(am[i], am[i]);
                ffma2(acc[i][0], ad, w01);
                ffma2(acc[i][1], ad, w23);
                ffma2(acc[i][2], ad, w45);
                ffma2(acc[i][3], ad, w67);
            }
        }
    }
#pragma unroll
    for (int i = 0; i < 8; i++) {
        int m = m0 + mi + i;
        float* crow;
        if (mode == 1) {
            int t = m >> 5, b = m & 31;
            crow = C + (size_t)b * ((size_t)TT * VV) + (size_t)t * VV;
        } else {
            crow = C + (size_t)m * N;
        }
#pragma unroll
        for (int j = 0; j < 4; j++) {
            float lo, hi;
            upk2(acc[i][j], lo, hi);
            int n = n0 + ni + j * 2;
            crow[n] = lo + bias[n];
            crow[n + 1] = hi + bias[n + 1];
        }
    }
}

// ---------------- per-step tile GEMM: C[32 x 32cols] = A[32,1024] @ W^T ----------
__device__ __forceinline__ void tile32(
    float (*As)[132], float (*Ws)[132],
    const float* __restrict__ A, int lda,
    const float* __restrict__ W, int ldw, int n0,
    const float* __restrict__ bias,
    const float* __restrict__ init, int ldi,
    float* __restrict__ C, int ldc, int tid)
{
    const int ml = tid >> 3;          // 0..31
    const int cl = tid & 7;           // 0..7
    const int kb = cl * 4;
    ull acc[4] = {0ull, 0ull, 0ull, 0ull};
    float4 ra[4], rw[4];
    const float* Arow = A + (size_t)ml * lda;
    const float* Wrow = W + (size_t)(n0 + ml) * ldw;

#pragma unroll
    for (int j = 0; j < 4; j++) {
        ra[j] = *(const float4*)(Arow + kb + j * 32);
        rw[j] = *(const float4*)(Wrow + kb + j * 32);
    }
    for (int ck = 0; ck < HH / KC; ck++) {
        __syncthreads();
#pragma unroll
        for (int j = 0; j < 4; j++) {
            *(float4*)&As[ml][kb + j * 32] = ra[j];
            *(float4*)&Ws[ml][kb + j * 32] = rw[j];
        }
        __syncthreads();
        if (ck + 1 < HH / KC) {
            int kc = (ck + 1) * KC;
#pragma unroll
            for (int j = 0; j < 4; j++) {
                ra[j] = *(const float4*)(Arow + kc + kb + j * 32);
                rw[j] = *(const float4*)(Wrow + kc + kb + j * 32);
            }
        }
#pragma unroll 16
        for (int k = 0; k < KC; k += 4) {
            ULL2 a = *(const ULL2*)&As[ml][k];
#pragma unroll
            for (int j = 0; j < 4; j++) {
                ULL2 w = *(const ULL2*)&Ws[cl + j * 8][k];
                ffma2(acc[j], a.x, w.x);
                ffma2(acc[j], a.y, w.y);
            }
        }
    }
#pragma unroll
    for (int j = 0; j < 4; j++) {
        float lo, hi;
        upk2(acc[j], lo, hi);
        int n = n0 + cl + j * 8;
        float v = lo + hi;
        if (bias) v += bias[n];
        if (init) v += init[(size_t)ml * ldi + n];
        C[(size_t)ml * ldc + n] = v;
    }
}

// ---------------- persistent recurrence: all 64 steps in one kernel --------------
__global__ __launch_bounds__(256, 1)
void recur(const float* __restrict__ h0, const float* __restrict__ enc,
           const float* __restrict__ Wa_w, const float* __restrict__ Wa_b,
           const float* __restrict__ W_hh, const float* __restrict__ b_hh,
           const float* __restrict__ W_ih,
           const float* __restrict__ Va_w, const float* __restrict__ Va_b,
           float* __restrict__ attn_out, float* __restrict__ hT_out)
{
    __shared__ float As[32][132];
    __shared__ float Ws[32][132];
    __shared__ float smq[HH];
    __shared__ float smva[HH];
    __shared__ float smsc[SS];
    __shared__ float smex[SS];

    const int blk = blockIdx.x;
    const int tid = threadIdx.x;
    unsigned bt = 0;

    for (int t = 0; t < TT; t++) {
        const float* hid = (t == 0) ? h0 : (g_Hall + (size_t)(t - 1) * BB * HH);

        // phase A: q (tasks 0..31) + GH (tasks 32..127)
        if (blk < 128) {
            if (blk < 32)
                tile32(As, Ws, hid, HH, Wa_w, HH, blk * 32, Wa_b,
                       nullptr, 0, g_Q, HH, tid);
            else
                tile32(As, Ws, hid, HH, W_hh, HH, (blk - 32) * 32, b_hh,
                       nullptr, 0, g_GH, G3H, tid);
        }
        bt += NBLK; gridbar(bt);

        // phase B1: scores[b][s] = Va . tanh(q[b] + Uk[b,s]) + Va_b
        if (blk < 128) {
            const int b = blk >> 2, sg = (blk & 3) * 16;
            for (int i = tid; i < HH; i += 256) {
                smq[i] = g_Q[b * HH + i];
                smva[i] = Va_w[i];
            }
            __syncthreads();
            const int w = tid >> 5, lane = tid & 31;
#pragma unroll
            for (int si = 0; si < 2; si++) {
                int s = sg + w * 2 + si;
                const float* uk = g_Uk + (size_t)(b * SS + s) * HH;
                float sum = 0.f;
#pragma unroll 8
                for (int h = lane; h < HH; h += 32)
                    sum += smva[h] * tanh_ap(smq[h] + uk[h]);
#pragma unroll
                for (int o = 16; o; o >>= 1)
                    sum += __shfl_xor_sync(0xffffffffu, sum, o);
                if (lane == 0) g_Sc[b * SS + s] = sum + Va_b[0];
            }
        }
        bt += NBLK; gridbar(bt);

        // phase B2: softmax + attentions output + context (h-quartered)
        if (blk < 128) {
            const int b = blk >> 2, hq = blk & 3;
            if (tid < SS) smsc[tid] = g_Sc[b * SS + tid];
            __syncthreads();
            float mx = -1e30f;
#pragma unroll
            for (int s = 0; s < SS; s++) mx = fmaxf(mx, smsc[s]);
            if (tid < SS) smex[tid] = expf(smsc[tid] - mx);
            __syncthreads();
            float sum = 0.f;
#pragma unroll
            for (int s = 0; s < SS; s++) sum += smex[s];
            const float inv = 1.f / sum;
            const int h = hq * 256 + tid;
            const float* eb = enc + (size_t)b * SS * HH + h;
            float acc = 0.f;
#pragma unroll 8
            for (int s = 0; s < SS; s++) acc += smex[s] * eb[(size_t)s * HH];
            g_Ctx[b * HH + h] = acc * inv;
            if (hq == 0 && tid < SS)
                attn_out[(size_t)b * TT * SS + (size_t)t * SS + tid] = smex[tid] * inv;
        }
        bt += NBLK; gridbar(bt);

        // phase C: GI = GiX[t] + ctx @ W_ih[:, H:]^T   (96 tile tasks)
        if (blk < 96) {
            tile32(As, Ws, g_Ctx, HH, W_ih + HH, 2 * HH, blk * 32, nullptr,
                   g_GiX + (size_t)t * BB * G3H, G3H, g_GI, G3H, tid);
        }
        bt += NBLK; gridbar(bt);

        // phase D: GRU combine (PyTorch semantics)
        if (blk < 32) {
            const int b = blk;
            for (int h = tid; h < HH; h += 256) {
                float ir = g_GI[b * G3H + h],           hr = g_GH[b * G3H + h];
                float iz = g_GI[b * G3H + HH + h],      hz = g_GH[b * G3H + HH + h];
                float in_ = g_GI[b * G3H + 2 * HH + h], hn = g_GH[b * G3H + 2 * HH + h];
                float r = 1.f / (1.f + expf(-(ir + hr)));
                float z = 1.f / (1.f + expf(-(iz + hz)));
                float nv = tanhf(in_ + r * hn);
                float hnew = (1.f - z) * nv + z * hid[b * HH + h];
                g_Hall[(size_t)t * BB * HH + b * HH + h] = hnew;
                if (t == TT - 1) hT_out[b * HH + h] = hnew;
            }
        }
        bt += NBLK; gridbar(bt);
    }
}

// tokens: tok(b,0)=SOS=1, tok(b,t)=target[b,t-1]; gather emb rows; reset barrier
__global__ __launch_bounds__(256)
void gather_emb(const int* __restrict__ target, const float* __restrict__ emb)
{
    if (blockIdx.x == 0 && threadIdx.x == 0) g_arrive = 0;  // stream-ordered reset
    const int r = blockIdx.x;            // r = t*32 + b
    const int t = r >> 5, b = r & 31;
    const int tok = (t == 0) ? 1 : target[b * TT + (t - 1)];
    const float4* src = (const float4*)(emb + (size_t)tok * HH);
    float4* dst = (float4*)(g_X + (size_t)r * HH);
    dst[threadIdx.x] = src[threadIdx.x];
}

extern "C" void kernel_launch(void* const* d_in, const int* in_sizes, int n_in,
                              void* d_out, int out_size)
{
    (void)in_sizes; (void)n_in; (void)out_size;
    const float* enc   = (const float*)d_in[0];
    const float* h0    = (const float*)d_in[1];
    const int*   tgt   = (const int*)d_in[2];
    const float* emb   = (const float*)d_in[3];
    const float* Wa_w  = (const float*)d_in[4];
    const float* Wa_b  = (const float*)d_in[5];
    const float* Ua_w  = (const float*)d_in[6];
    const float* Ua_b  = (const float*)d_in[7];
    const float* Va_w  = (const float*)d_in[8];
    const float* Va_b  = (const float*)d_in[9];
    const float* W_ih  = (const float*)d_in[10];
    const float* W_hh  = (const float*)d_in[11];
    const float* b_ih  = (const float*)d_in[12];
    const float* b_hh  = (const float*)d_in[13];
    const float* out_w = (const float*)d_in[14];
    const float* out_b = (const float*)d_in[15];

    float* out = (float*)d_out;
    float* dec_out  = out;                                          // B*T*V
    float* hT_out   = out + (size_t)BB * TT * VV;                   // B*H
    float* attn_out = out + (size_t)BB * TT * VV + (size_t)BB * HH; // B*T*S

    float *Uk, *X, *GiX, *Hall;
    cudaGetSymbolAddress((void**)&Uk, g_Uk);
    cudaGetSymbolAddress((void**)&X, g_X);
    cudaGetSymbolAddress((void**)&GiX, g_GiX);
    cudaGetSymbolAddress((void**)&Hall, g_Hall);

    // Phase 0: loop-invariant precomputation (also resets grid-barrier counter)
    gather_emb<<<TT * BB, 256>>>(tgt, emb);
    gemm128<<<dim3(HH / 128, (BB * SS) / 128), 256>>>(enc, Ua_w, HH, Ua_b, Uk, HH, 0);
    gemm128<<<dim3(G3H / 128, (TT * BB) / 128), 256>>>(X, W_ih, 2 * HH, b_ih, GiX, G3H, 0);

    // Phase 1: persistent fused recurrence (all 64 steps, grid-barrier phased)
    recur<<<NBLK, 256>>>(h0, enc, Wa_w, Wa_b, W_hh, b_hh, W_ih, Va_w, Va_b,
                         attn_out, hT_out);

    // Phase 2: one batched vocab projection for all 64 steps (out_w read ONCE)
    gemm128<<<dim3(VV / 128, (TT * BB) / 128), 256>>>(Hall, out_w, HH, out_b,
                                                      dec_out, VV, 1);
}

// round 10
// speedup vs baseline: 1.7198x; 1.4186x over previous
#include <cuda_runtime.h>
#include <cstdint>
#include <cstddef>

#define BB 32
#define SS 64
#define TT 64
#define HH 1024
#define VV 32000
#define G3H 3072
#define NBLK 148
#define KC 128

// ---------------- scratch (device globals; no allocation allowed) ----------------
__device__ float g_Uk[BB * SS * HH];
__device__ float g_X[TT * BB * HH];
__device__ float g_GiX[TT * BB * G3H];
__device__ float g_Hall[TT * BB * HH];
__device__ float g_Q[BB * HH];
__device__ float g_GH[BB * G3H];
__device__ float g_GI[BB * G3H];
__device__ float g_Ctx[BB * HH];
__device__ float g_Sc[BB * SS];
__device__ unsigned g_arrive;

// ---------------- helpers ----------------
typedef unsigned long long ull;
struct __align__(16) ULL2 { ull x, y; };

__device__ __forceinline__ ull pk2(float lo, float hi) {
    ull r; asm("mov.b64 %0, {%1, %2};" : "=l"(r) : "f"(lo), "f"(hi)); return r;
}
__device__ __forceinline__ void upk2(ull v, float& lo, float& hi) {
    asm("mov.b64 {%0, %1}, %2;" : "=f"(lo), "=f"(hi) : "l"(v));
}
__device__ __forceinline__ void ffma2(ull& c, ull a, ull b) {
    asm("fma.rn.f32x2 %0, %1, %2, %0;" : "+l"(c) : "l"(a), "l"(b));
}
__device__ __forceinline__ float tanh_ap(float x) {
    float y; asm("tanh.approx.f32 %0, %1;" : "=f"(y) : "f"(x)); return y;
}
__device__ __forceinline__ unsigned ld_acq(unsigned* p) {
    unsigned v;
    asm volatile("ld.acquire.gpu.global.u32 %0, [%1];" : "=r"(v) : "l"(p) : "memory");
    return v;
}
__device__ __forceinline__ void gridbar(unsigned target) {
    __syncthreads();
    if (threadIdx.x == 0) {
        __threadfence();
        atomicAdd(&g_arrive, 1u);
        while (ld_acq(&g_arrive) < target) { __nanosleep(64); }
    }
    __syncthreads();
}
__device__ __forceinline__ unsigned t32(float x) {   // round-to-nearest tf32
    unsigned r; asm("cvt.rna.tf32.f32 %0, %1;" : "=r"(r) : "f"(x)); return r;
}
__device__ __forceinline__ void mma8(float& c0, float& c1, float& c2, float& c3,
                                     unsigned a0, unsigned a1, unsigned a2, unsigned a3,
                                     unsigned b0, unsigned b1) {
    asm volatile(
        "mma.sync.aligned.m16n8k8.row.col.f32.tf32.tf32.f32 "
        "{%0,%1,%2,%3}, {%4,%5,%6,%7}, {%8,%9}, {%0,%1,%2,%3};"
        : "+f"(c0), "+f"(c1), "+f"(c2), "+f"(c3)
        : "r"(a0), "r"(a1), "r"(a2), "r"(a3), "r"(b0), "r"(b1));
}

// =================================================================================
// tf32 tensor-core GEMM: C[M,N] = A[M,1024] (lda) * W[N,1024] (ldw)^T + bias
// block 128x128, 256 thr = 8 warps (2m x 4n), warp 64x32, K-chunk 32.
// grid: (x = M/128, y = N/128) so consecutive bids share the same W tile (L2 reuse).
// mode 0: C row-major ld=N.  mode 1: logits remap row r=t*32+b -> C[b][t*VV + n].
// =================================================================================
__global__ __launch_bounds__(256)
void gemmTC(const float* __restrict__ A, int lda,
            const float* __restrict__ W, int ldw,
            const float* __restrict__ bias, float* __restrict__ C, int N, int mode)
{
    __shared__ unsigned As[128][36];
    __shared__ unsigned Ws[128][36];
    const int tid = threadIdx.x;
    const int m0 = blockIdx.x * 128;
    const int n0 = blockIdx.y * 128;
    const int wid = tid >> 5, lane = tid & 31;
    const int gid = lane >> 2, tig = lane & 3;   // groupID / threadID_in_group
    const int wm = (wid >> 2) * 64;              // warp m base in tile
    const int wn = (wid & 3) * 32;               // warp n base in tile

    // loader mapping: row = tid>>1 (0..127), 16-col half = (tid&1)*16
    const int lrow = tid >> 1;
    const int lcb = (tid & 1) << 4;
    const float* Arow = A + (size_t)(m0 + lrow) * lda + lcb;
    const float* Wrow = W + (size_t)(n0 + lrow) * ldw + lcb;

    float acc[4][4][4];
#pragma unroll
    for (int i = 0; i < 4; i++)
#pragma unroll
        for (int j = 0; j < 4; j++)
#pragma unroll
            for (int e = 0; e < 4; e++) acc[i][j][e] = 0.f;

    float4 ra[4], rw[4];
#pragma unroll
    for (int j = 0; j < 4; j++) {
        ra[j] = *(const float4*)(Arow + j * 4);
        rw[j] = *(const float4*)(Wrow + j * 4);
    }

    for (int ck = 0; ck < HH / 32; ck++) {
        __syncthreads();
#pragma unroll
        for (int j = 0; j < 4; j++) {
            As[lrow][lcb + j * 4 + 0] = t32(ra[j].x);
            As[lrow][lcb + j * 4 + 1] = t32(ra[j].y);
            As[lrow][lcb + j * 4 + 2] = t32(ra[j].z);
            As[lrow][lcb + j * 4 + 3] = t32(ra[j].w);
            Ws[lrow][lcb + j * 4 + 0] = t32(rw[j].x);
            Ws[lrow][lcb + j * 4 + 1] = t32(rw[j].y);
            Ws[lrow][lcb + j * 4 + 2] = t32(rw[j].z);
            Ws[lrow][lcb + j * 4 + 3] = t32(rw[j].w);
        }
        __syncthreads();
        if (ck + 1 < HH / 32) {
            int kt = (ck + 1) * 32;
#pragma unroll
            for (int j = 0; j < 4; j++) {
                ra[j] = *(const float4*)(Arow + kt + j * 4);
                rw[j] = *(const float4*)(Wrow + kt + j * 4);
            }
        }
#pragma unroll
        for (int kk = 0; kk < 32; kk += 8) {
            unsigned af[4][4], bf[4][2];
#pragma unroll
            for (int mf = 0; mf < 4; mf++) {
                int r = wm + mf * 16 + gid;
                af[mf][0] = As[r][kk + tig];
                af[mf][1] = As[r + 8][kk + tig];
                af[mf][2] = As[r][kk + tig + 4];
                af[mf][3] = As[r + 8][kk + tig + 4];
            }
#pragma unroll
            for (int nf = 0; nf < 4; nf++) {
                int c = wn + nf * 8 + gid;
                bf[nf][0] = Ws[c][kk + tig];
                bf[nf][1] = Ws[c][kk + tig + 4];
            }
#pragma unroll
            for (int mf = 0; mf < 4; mf++)
#pragma unroll
                for (int nf = 0; nf < 4; nf++)
                    mma8(acc[mf][nf][0], acc[mf][nf][1], acc[mf][nf][2], acc[mf][nf][3],
                         af[mf][0], af[mf][1], af[mf][2], af[mf][3],
                         bf[nf][0], bf[nf][1]);
        }
    }

    // epilogue: bias add + (optional) logits row remap; rows r and r+8 per frag
#pragma unroll
    for (int mf = 0; mf < 4; mf++) {
#pragma unroll
        for (int rr = 0; rr < 2; rr++) {
            int m = m0 + wm + mf * 16 + gid + rr * 8;
            float* crow;
            if (mode == 1) {
                int tt = m >> 5, b = m & 31;
                crow = C + (size_t)b * ((size_t)TT * VV) + (size_t)tt * VV;
            } else {
                crow = C + (size_t)m * N;
            }
#pragma unroll
            for (int nf = 0; nf < 4; nf++) {
                int n = n0 + wn + nf * 8 + tig * 2;
                float2 v;
                v.x = acc[mf][nf][rr * 2 + 0] + bias[n];
                v.y = acc[mf][nf][rr * 2 + 1] + bias[n + 1];
                *(float2*)(crow + n) = v;
            }
        }
    }
}

// ---------------- per-step tile GEMM: C[32 x 32cols] = A[32,1024] @ W^T ----------
__device__ __forceinline__ void tile32(
    float (*As)[132], float (*Ws)[132],
    const float* __restrict__ A, int lda,
    const float* __restrict__ W, int ldw, int n0,
    const float* __restrict__ bias,
    const float* __restrict__ init, int ldi,
    float* __restrict__ C, int ldc, int tid)
{
    const int ml = tid >> 3;
    const int cl = tid & 7;
    const int kb = cl * 4;
    ull acc[4] = {0ull, 0ull, 0ull, 0ull};
    float4 ra[4], rw[4];
    const float* Arow = A + (size_t)ml * lda;
    const float* Wrow = W + (size_t)(n0 + ml) * ldw;

#pragma unroll
    for (int j = 0; j < 4; j++) {
        ra[j] = *(const float4*)(Arow + kb + j * 32);
        rw[j] = *(const float4*)(Wrow + kb + j * 32);
    }
    for (int ck = 0; ck < HH / KC; ck++) {
        __syncthreads();
#pragma unroll
        for (int j = 0; j < 4; j++) {
            *(float4*)&As[ml][kb + j * 32] = ra[j];
            *(float4*)&Ws[ml][kb + j * 32] = rw[j];
        }
        __syncthreads();
        if (ck + 1 < HH / KC) {
            int kc = (ck + 1) * KC;
#pragma unroll
            for (int j = 0; j < 4; j++) {
                ra[j] = *(const float4*)(Arow + kc + kb + j * 32);
                rw[j] = *(const float4*)(Wrow + kc + kb + j * 32);
            }
        }
#pragma unroll 16
        for (int k = 0; k < KC; k += 4) {
            ULL2 a = *(const ULL2*)&As[ml][k];
#pragma unroll
            for (int j = 0; j < 4; j++) {
                ULL2 w = *(const ULL2*)&Ws[cl + j * 8][k];
                ffma2(acc[j], a.x, w.x);
                ffma2(acc[j], a.y, w.y);
            }
        }
    }
#pragma unroll
    for (int j = 0; j < 4; j++) {
        float lo, hi;
        upk2(acc[j], lo, hi);
        int n = n0 + cl + j * 8;
        float v = lo + hi;
        if (bias) v += bias[n];
        if (init) v += init[(size_t)ml * ldi + n];
        C[(size_t)ml * ldc + n] = v;
    }
}

// ---------------- persistent recurrence: all 64 steps in one kernel --------------
__global__ __launch_bounds__(256, 1)
void recur(const float* __restrict__ h0, const float* __restrict__ enc,
           const float* __restrict__ Wa_w, const float* __restrict__ Wa_b,
           const float* __restrict__ W_hh, const float* __restrict__ b_hh,
           const float* __restrict__ W_ih,
           const float* __restrict__ Va_w, const float* __restrict__ Va_b,
           float* __restrict__ attn_out, float* __restrict__ hT_out)
{
    __shared__ float As[32][132];
    __shared__ float Ws[32][132];
    __shared__ float smq[HH];
    __shared__ float smva[HH];
    __shared__ float smsc[SS];
    __shared__ float smex[SS];

    const int blk = blockIdx.x;
    const int tid = threadIdx.x;
    unsigned bt = 0;

    for (int t = 0; t < TT; t++) {
        const float* hid = (t == 0) ? h0 : (g_Hall + (size_t)(t - 1) * BB * HH);

        // phase A: q (tasks 0..31) + GH (tasks 32..127)
        if (blk < 128) {
            if (blk < 32)
                tile32(As, Ws, hid, HH, Wa_w, HH, blk * 32, Wa_b,
                       nullptr, 0, g_Q, HH, tid);
            else
                tile32(As, Ws, hid, HH, W_hh, HH, (blk - 32) * 32, b_hh,
                       nullptr, 0, g_GH, G3H, tid);
        }
        bt += NBLK; gridbar(bt);

        // phase B1: scores[b][s] = Va . tanh(q[b] + Uk[b,s]) + Va_b
        if (blk < 128) {
            const int b = blk >> 2, sg = (blk & 3) * 16;
            for (int i = tid; i < HH; i += 256) {
                smq[i] = g_Q[b * HH + i];
                smva[i] = Va_w[i];
            }
            __syncthreads();
            const int w = tid >> 5, lane = tid & 31;
#pragma unroll
            for (int si = 0; si < 2; si++) {
                int s = sg + w * 2 + si;
                const float* uk = g_Uk + (size_t)(b * SS + s) * HH;
                float sum = 0.f;
#pragma unroll 8
                for (int h = lane; h < HH; h += 32)
                    sum += smva[h] * tanh_ap(smq[h] + uk[h]);
#pragma unroll
                for (int o = 16; o; o >>= 1)
                    sum += __shfl_xor_sync(0xffffffffu, sum, o);
                if (lane == 0) g_Sc[b * SS + s] = sum + Va_b[0];
            }
        }
        bt += NBLK; gridbar(bt);

        // phase B2: softmax + attentions output + context (h-quartered)
        if (blk < 128) {
            const int b = blk >> 2, hq = blk & 3;
            if (tid < SS) smsc[tid] = g_Sc[b * SS + tid];
            __syncthreads();
            float mx = -1e30f;
#pragma unroll
            for (int s = 0; s < SS; s++) mx = fmaxf(mx, smsc[s]);
            if (tid < SS) smex[tid] = expf(smsc[tid] - mx);
            __syncthreads();
            float sum = 0.f;
#pragma unroll
            for (int s = 0; s < SS; s++) sum += smex[s];
            const float inv = 1.f / sum;
            const int h = hq * 256 + tid;
            const float* eb = enc + (size_t)b * SS * HH + h;
            float acc = 0.f;
#pragma unroll 8
            for (int s = 0; s < SS; s++) acc += smex[s] * eb[(size_t)s * HH];
            g_Ctx[b * HH + h] = acc * inv;
            if (hq == 0 && tid < SS)
                attn_out[(size_t)b * TT * SS + (size_t)t * SS + tid] = smex[tid] * inv;
        }
        bt += NBLK; gridbar(bt);

        // phase C: GI = GiX[t] + ctx @ W_ih[:, H:]^T   (96 tile tasks)
        if (blk < 96) {
            tile32(As, Ws, g_Ctx, HH, W_ih + HH, 2 * HH, blk * 32, nullptr,
                   g_GiX + (size_t)t * BB * G3H, G3H, g_GI, G3H, tid);
        }
        bt += NBLK; gridbar(bt);

        // phase D: GRU combine (PyTorch semantics)
        if (blk < 32) {
            const int b = blk;
            for (int h = tid; h < HH; h += 256) {
                float ir = g_GI[b * G3H + h],           hr = g_GH[b * G3H + h];
                float iz = g_GI[b * G3H + HH + h],      hz = g_GH[b * G3H + HH + h];
                float in_ = g_GI[b * G3H + 2 * HH + h], hn = g_GH[b * G3H + 2 * HH + h];
                float r = 1.f / (1.f + expf(-(ir + hr)));
                float z = 1.f / (1.f + expf(-(iz + hz)));
                float nv = tanhf(in_ + r * hn);
                float hnew = (1.f - z) * nv + z * hid[b * HH + h];
                g_Hall[(size_t)t * BB * HH + b * HH + h] = hnew;
                if (t == TT - 1) hT_out[b * HH + h] = hnew;
            }
        }
        bt += NBLK; gridbar(bt);
    }
}

// tokens: tok(b,0)=SOS=1, tok(b,t)=target[b,t-1]; gather emb rows; reset barrier
__global__ __launch_bounds__(256)
void gather_emb(const int* __restrict__ target, const float* __restrict__ emb)
{
    if (blockIdx.x == 0 && threadIdx.x == 0) g_arrive = 0;  // stream-ordered reset
    const int r = blockIdx.x;            // r = t*32 + b
    const int t = r >> 5, b = r & 31;
    const int tok = (t == 0) ? 1 : target[b * TT + (t - 1)];
    const float4* src = (const float4*)(emb + (size_t)tok * HH);
    float4* dst = (float4*)(g_X + (size_t)r * HH);
    dst[threadIdx.x] = src[threadIdx.x];
}

extern "C" void kernel_launch(void* const* d_in, const int* in_sizes, int n_in,
                              void* d_out, int out_size)
{
    (void)in_sizes; (void)n_in; (void)out_size;
    const float* enc   = (const float*)d_in[0];
    const float* h0    = (const float*)d_in[1];
    const int*   tgt   = (const int*)d_in[2];
    const float* emb   = (const float*)d_in[3];
    const float* Wa_w  = (const float*)d_in[4];
    const float* Wa_b  = (const float*)d_in[5];
    const float* Ua_w  = (const float*)d_in[6];
    const float* Ua_b  = (const float*)d_in[7];
    const float* Va_w  = (const float*)d_in[8];
    const float* Va_b  = (const float*)d_in[9];
    const float* W_ih  = (const float*)d_in[10];
    const float* W_hh  = (const float*)d_in[11];
    const float* b_ih  = (const float*)d_in[12];
    const float* b_hh  = (const float*)d_in[13];
    const float* out_w = (const float*)d_in[14];
    const float* out_b = (const float*)d_in[15];

    float* out = (float*)d_out;
    float* dec_out  = out;                                          // B*T*V
    float* hT_out   = out + (size_t)BB * TT * VV;                   // B*H
    float* attn_out = out + (size_t)BB * TT * VV + (size_t)BB * HH; // B*T*S

    float *Uk, *X, *GiX, *Hall;
    cudaGetSymbolAddress((void**)&Uk, g_Uk);
    cudaGetSymbolAddress((void**)&X, g_X);
    cudaGetSymbolAddress((void**)&GiX, g_GiX);
    cudaGetSymbolAddress((void**)&Hall, g_Hall);

    // Phase 0: loop-invariant precomputation (also resets grid-barrier counter)
    gather_emb<<<TT * BB, 256>>>(tgt, emb);
    // Uk = enc @ Ua^T + Ua_b        [2048 x 1024], K=1024
    gemmTC<<<dim3((BB * SS) / 128, HH / 128), 256>>>(enc, HH, Ua_w, HH, Ua_b, Uk, HH, 0);
    // GiX = X @ W_ih[:, :H]^T + b_ih  [2048 x 3072], K=1024 (ldw = 2H)
    gemmTC<<<dim3((TT * BB) / 128, G3H / 128), 256>>>(X, HH, W_ih, 2 * HH, b_ih, GiX, G3H, 0);

    // Phase 1: persistent fused recurrence (all 64 steps, grid-barrier phased)
    recur<<<NBLK, 256>>>(h0, enc, Wa_w, Wa_b, W_hh, b_hh, W_ih, Va_w, Va_b,
                         attn_out, hT_out);

    // Phase 2: one batched vocab projection for all 64 steps (tensor cores, tf32)
    gemmTC<<<dim3((TT * BB) / 128, VV / 128), 256>>>(Hall, HH, out_w, HH, out_b,
                                                     dec_out, VV, 1);
}